// round 7
// baseline (speedup 1.0000x reference)
#include <cuda_runtime.h>

// out = feat @ Wv + bv
//
// The reference's softmax over axis=-2 (j) followed by einsum('ijk,ik->ik')
// (a sum over j) makes the attention-weight branch sum to exactly 1 per
// (i,k), so out[i,k] == v[i,k] == (feat @ Wv + bv)[i,k].
//
// feat: [N=1024, C=256] f32   (d_in[0])
// Wv:   [C, C]          f32   (d_in[9])
// bv:   [C]             f32   (d_in[10])
// out:  [N, C]          f32

namespace {

constexpr int Ndim = 1024;
constexpr int Cdim = 256;
constexpr int TM = 64;    // rows per block
constexpr int TN = 32;    // cols per block
constexpr int KC = 64;    // k-chunk (4 chunks, double-buffered smem)
constexpr int CHUNKS = Cdim / KC;
constexpr int KU = 8;     // k-unroll group: 16 batched LDS then 64 FFMA
constexpr int SAT_STRIDE = TM + 4;  // 68 floats: 16B-aligned rows

// 256 threads = 8 warps = 2 warps/SMSP, 4x2 micro-tile.
// The inner loop processes k in groups of 8: ALL 16 shared loads for the
// group are issued back-to-back first (one 29-cyc latency exposure per
// group, loads pipelined), then 64 FFMAs run on resident registers. Per
// group a warp needs ~60 cyc of non-FMA time vs. a 128-cyc FMA-pipe share
// at 2 warps/SMSP — latency fully hidden, FMA pipe becomes the binder.

__global__ __launch_bounds__(256, 1)
void vgemm_bias_kernel(const float* __restrict__ A,    // [N, C] feat
                       const float* __restrict__ B,    // [C, C] Wv
                       const float* __restrict__ bias, // [C]
                       float* __restrict__ O)          // [N, C]
{
    __shared__ float sAT[2][KC][SAT_STRIDE];  // A tile, k-major (transposed)
    __shared__ float sB [2][KC][TN];          // B tile, k-major

    const int tid  = threadIdx.x;   // 0..255
    const int lane = tid & 31;
    const int warp = tid >> 5;      // 0..7
    const int tn   = tid & 15;      // col group (x2)
    const int tm   = tid >> 4;      // row group (x4)

    const int row0 = blockIdx.y * TM;
    const int col0 = blockIdx.x * TN;

    // ---- tile loaders (global -> smem) ----
    auto load_tiles = [&](int kk, int buf) {
        // A: transpose during load. Unit u covers rows m0..m0+3, 32 k's.
        #pragma unroll
        for (int i = 0; i < 4; i++) {
            const int u  = warp * 4 + i;           // 0..31
            const int m0 = (u & 15) * 4;           // 0,4,...,60
            const int k  = ((u >> 4) << 5) + lane; // 0..63
            const float* gp = &A[(row0 + m0) * Cdim + kk + k];
            float4 v;
            v.x = gp[0 * Cdim];
            v.y = gp[1 * Cdim];
            v.z = gp[2 * Cdim];
            v.w = gp[3 * Cdim];
            *reinterpret_cast<float4*>(&sAT[buf][k][m0]) = v;
        }
        // B tile: 64 k x 32 n = 512 float4; 2 per thread, fully coalesced.
        #pragma unroll
        for (int i = 0; i < 2; i++) {
            const int idx = i * 256 + tid;   // 0..511
            const int r   = idx >> 3;        // 8 float4 per row
            const int c4  = (idx & 7) * 4;
            *reinterpret_cast<float4*>(&sB[buf][r][c4]) =
                *reinterpret_cast<const float4*>(&B[(kk + r) * Cdim + col0 + c4]);
        }
    };

    float acc[4][2];
    #pragma unroll
    for (int r = 0; r < 4; r++) {
        acc[r][0] = 0.f;
        acc[r][1] = 0.f;
    }

    load_tiles(0, 0);
    __syncthreads();

    for (int chunk = 0; chunk < CHUNKS; chunk++) {   // rolled
        const int buf = chunk & 1;

        // kick off next chunk's global loads first (longest latency)
        if (chunk + 1 < CHUNKS)
            load_tiles((chunk + 1) * KC, buf ^ 1);

        #pragma unroll
        for (int kg = 0; kg < KC; kg += KU) {
            // ---- batch: 16 back-to-back shared loads for 8 k-iters ----
            float4 a[KU];
            float2 b[KU];
            #pragma unroll
            for (int u = 0; u < KU; u++) {
                a[u] = *reinterpret_cast<const float4*>(&sAT[buf][kg + u][tm * 4]);
                b[u] = *reinterpret_cast<const float2*>(&sB [buf][kg + u][tn * 2]);
            }
            // ---- 64 FFMAs on resident registers ----
            #pragma unroll
            for (int u = 0; u < KU; u++) {
                acc[0][0] = fmaf(a[u].x, b[u].x, acc[0][0]);
                acc[0][1] = fmaf(a[u].x, b[u].y, acc[0][1]);
                acc[1][0] = fmaf(a[u].y, b[u].x, acc[1][0]);
                acc[1][1] = fmaf(a[u].y, b[u].y, acc[1][1]);
                acc[2][0] = fmaf(a[u].z, b[u].x, acc[2][0]);
                acc[2][1] = fmaf(a[u].z, b[u].y, acc[2][1]);
                acc[3][0] = fmaf(a[u].w, b[u].x, acc[3][0]);
                acc[3][1] = fmaf(a[u].w, b[u].y, acc[3][1]);
            }
        }
        __syncthreads();
    }

    // ---- epilogue: bias add + float2 stores ----
    const int col = col0 + tn * 2;
    const float2 bv2 = *reinterpret_cast<const float2*>(&bias[col]);
    #pragma unroll
    for (int r = 0; r < 4; r++) {
        const int row = row0 + tm * 4 + r;
        float2 o;
        o.x = acc[r][0] + bv2.x;
        o.y = acc[r][1] + bv2.y;
        *reinterpret_cast<float2*>(&O[row * Cdim + col]) = o;
    }
}

} // namespace

extern "C" void kernel_launch(void* const* d_in, const int* in_sizes, int n_in,
                              void* d_out, int out_size)
{
    const float* feat = (const float*)d_in[0];
    const float* Wv   = (const float*)d_in[9];
    const float* bv   = (const float*)d_in[10];
    float* out        = (float*)d_out;

    dim3 grid(Cdim / TN, Ndim / TM);   // (8, 16) = 128 blocks
    dim3 block(256);
    vgemm_bias_kernel<<<grid, block>>>(feat, Wv, bv, out);
}

// round 8
// speedup vs baseline: 1.0025x; 1.0025x over previous
#include <cuda_runtime.h>

// out = feat @ Wv + bv
//
// The reference's softmax over axis=-2 (j) followed by einsum('ijk,ik->ik')
// (a sum over j) makes the attention-weight branch sum to exactly 1 per
// (i,k), so out[i,k] == v[i,k] == (feat @ Wv + bv)[i,k].
//
// feat: [N=1024, C=256] f32   (d_in[0])
// Wv:   [C, C]          f32   (d_in[9])
// bv:   [C]             f32   (d_in[10])
// out:  [N, C]          f32
//
// This round: packed fma.rn.f32x2 (SASS FFMA2, PTX-only per SASS_QUICKREF)
// with an A tile stored DUPLICATED ({v,v} pairs) in smem so the vector
// operand needs no per-iteration packing. 32 FMAs per 11 instructions.

namespace {

constexpr int Ndim = 1024;
constexpr int Cdim = 256;
constexpr int TM = 64;    // rows per block
constexpr int TN = 32;    // cols per block
constexpr int KC = 32;    // k-chunk (8 chunks, double-buffered smem)
constexpr int CHUNKS = Cdim / KC;
constexpr int SATD_STRIDE = 2 * TM + 4;  // 132 floats = 528 B (16B-aligned rows)

// packed f32x2 fma: c = a*b + c (elementwise on 2-float pairs in a 64-bit reg)
#define FMA2(c, a, b) \
    asm("fma.rn.f32x2 %0, %1, %2, %3;" : "=l"(c) : "l"(a), "l"(b), "l"(c))

__device__ __forceinline__ float2 u64_as_f2(unsigned long long v) {
    float2 r;
    asm("mov.b64 {%0, %1}, %2;" : "=f"(r.x), "=f"(r.y) : "l"(v));
    return r;
}

// 128 threads = 4 warps (1/SMSP). Micro-tile 4 rows x 4 cols per thread,
// accumulated as 8 packed f32x2 registers. Grid = 128 blocks = 1/SM.

__global__ __launch_bounds__(128, 1)
void vgemm_bias_kernel(const float* __restrict__ A,    // [N, C] feat
                       const float* __restrict__ B,    // [C, C] Wv
                       const float* __restrict__ bias, // [C]
                       float* __restrict__ O)          // [N, C]
{
    // A tile, k-major, value-duplicated: row k holds {a0,a0,a1,a1,...}
    __shared__ float sATd[2][KC][SATD_STRIDE];  // 2*32*132*4 = 33.8 KB
    __shared__ float sB  [2][KC][TN];           // 2*32*32*4  =  8  KB

    const int tid  = threadIdx.x;   // 0..127
    const int lane = tid & 31;
    const int warp = tid >> 5;      // 0..3
    const int tn   = tid & 7;       // col group (x4)
    const int tm   = tid >> 3;      // row group (x4), 0..15

    const int row0 = blockIdx.y * TM;
    const int col0 = blockIdx.x * TN;

    // ---- tile loaders (global -> smem) ----
    auto load_tiles = [&](int kk, int buf) {
        // A: transpose + duplicate during load. Unit u covers rows
        // m0..m0+3 across the full 32-wide k-slice (k = lane).
        #pragma unroll
        for (int i = 0; i < 4; i++) {
            const int u  = warp * 4 + i;   // 0..15
            const int m0 = u * 4;          // 0,4,...,60
            const int k  = lane;           // 0..31
            const float* gp = &A[(row0 + m0) * Cdim + kk + k];
            const float v0 = gp[0 * Cdim];
            const float v1 = gp[1 * Cdim];
            const float v2 = gp[2 * Cdim];
            const float v3 = gp[3 * Cdim];
            float4 w0 = make_float4(v0, v0, v1, v1);
            float4 w1 = make_float4(v2, v2, v3, v3);
            *reinterpret_cast<float4*>(&sATd[buf][k][2 * m0])     = w0;
            *reinterpret_cast<float4*>(&sATd[buf][k][2 * m0 + 4]) = w1;
        }
        // B tile: 32 k x 32 n = 256 float4; 2 per thread, coalesced.
        #pragma unroll
        for (int i = 0; i < 2; i++) {
            const int idx = i * 128 + tid;   // 0..255
            const int r   = idx >> 3;        // 8 float4 per row
            const int c4  = (idx & 7) * 4;
            *reinterpret_cast<float4*>(&sB[buf][r][c4]) =
                *reinterpret_cast<const float4*>(&B[(kk + r) * Cdim + col0 + c4]);
        }
    };

    // acc[r][cp]: packed pair over columns (2*cp, 2*cp+1), rows r = 0..3
    unsigned long long acc[4][2];
    #pragma unroll
    for (int r = 0; r < 4; r++) {
        acc[r][0] = 0ull;
        acc[r][1] = 0ull;
    }

    load_tiles(0, 0);
    __syncthreads();

    for (int chunk = 0; chunk < CHUNKS; chunk++) {
        const int buf = chunk & 1;

        if (chunk + 1 < CHUNKS)
            load_tiles((chunk + 1) * KC, buf ^ 1);

        #pragma unroll
        for (int k = 0; k < KC; k++) {
            // {a0,a0},{a1,a1} and {a2,a2},{a3,a3} — pre-duplicated in smem
            const ulonglong2 a01 =
                *reinterpret_cast<const ulonglong2*>(&sATd[buf][k][tm * 8]);
            const ulonglong2 a23 =
                *reinterpret_cast<const ulonglong2*>(&sATd[buf][k][tm * 8 + 4]);
            // {b0,b1},{b2,b3}
            const ulonglong2 bp =
                *reinterpret_cast<const ulonglong2*>(&sB[buf][k][tn * 4]);

            FMA2(acc[0][0], a01.x, bp.x);
            FMA2(acc[0][1], a01.x, bp.y);
            FMA2(acc[1][0], a01.y, bp.x);
            FMA2(acc[1][1], a01.y, bp.y);
            FMA2(acc[2][0], a23.x, bp.x);
            FMA2(acc[2][1], a23.x, bp.y);
            FMA2(acc[3][0], a23.y, bp.x);
            FMA2(acc[3][1], a23.y, bp.y);
        }
        __syncthreads();
    }

    // ---- epilogue: unpack, bias add, float4 store ----
    const int col = col0 + tn * 4;
    const float4 bv4 = *reinterpret_cast<const float4*>(&bias[col]);
    #pragma unroll
    for (int r = 0; r < 4; r++) {
        const float2 lo = u64_as_f2(acc[r][0]);
        const float2 hi = u64_as_f2(acc[r][1]);
        float4 o;
        o.x = lo.x + bv4.x;
        o.y = lo.y + bv4.y;
        o.z = hi.x + bv4.z;
        o.w = hi.y + bv4.w;
        *reinterpret_cast<float4*>(&O[(row0 + tm * 4 + r) * Cdim + col]) = o;
    }
}

} // namespace

extern "C" void kernel_launch(void* const* d_in, const int* in_sizes, int n_in,
                              void* d_out, int out_size)
{
    const float* feat = (const float*)d_in[0];
    const float* Wv   = (const float*)d_in[9];
    const float* bv   = (const float*)d_in[10];
    float* out        = (float*)d_out;

    dim3 grid(Cdim / TN, Ndim / TM);   // (8, 16) = 128 blocks
    dim3 block(128);
    vgemm_bias_kernel<<<grid, block>>>(feat, Wv, bv, out);
}

// round 9
// speedup vs baseline: 1.0251x; 1.0226x over previous
#include <cuda_runtime.h>
#include <cstdint>

// out = feat @ Wv + bv
//
// The reference's softmax over axis=-2 (j) followed by einsum('ijk,ik->ik')
// (a sum over j) makes the attention-weight branch sum to exactly 1 per
// (i,k), so out[i,k] == v[i,k] == (feat @ Wv + bv)[i,k].
//
// feat: [N=1024, C=256] f32   (d_in[0])
// Wv:   [C, C]          f32   (d_in[9])
// bv:   [C]             f32   (d_in[10])
// out:  [N, C]          f32
//
// R9: FFMA2 (packed fma.rn.f32x2) + 2 warps/SMSP + asm-volatile-batched
// shared loads (ptxas cannot collapse them) + register-staged global
// double-buffering (LDG before compute, STS after).

namespace {

constexpr int Ndim = 1024;
constexpr int Cdim = 256;
constexpr int TM = 64;     // rows per block
constexpr int TN = 32;     // cols per block
constexpr int KC = 32;     // k-chunk (8 chunks)
constexpr int CHUNKS = Cdim / KC;
constexpr int KU = 4;      // k-group: 8 batched LDS.128 then 16 FFMA2
constexpr int SATD_STRIDE = 2 * TM + 4;  // 132 floats = 528 B, 16B-aligned

// packed f32x2 fma: c = a*b + c
#define FMA2(c, a, b) \
    asm("fma.rn.f32x2 %0, %1, %2, %3;" : "=l"(c) : "l"(a), "l"(b), "l"(c))

// one LDS.128 -> two 64-bit packed registers; volatile so the batch of
// loads issued per k-group cannot be sunk to their consumers by ptxas.
__device__ __forceinline__ void lds_2x64(unsigned long long& x,
                                         unsigned long long& y,
                                         uint32_t addr) {
    asm volatile("ld.shared.v2.u64 {%0, %1}, [%2];"
                 : "=l"(x), "=l"(y) : "r"(addr));
}

__device__ __forceinline__ float2 u64_as_f2(unsigned long long v) {
    float2 r;
    asm("mov.b64 {%0, %1}, %2;" : "=f"(r.x), "=f"(r.y) : "l"(v));
    return r;
}

// 256 threads = 8 warps = 2 warps/SMSP. Per-thread micro-tile: 2 rows x 4
// cols. A is stored value-duplicated in smem ({a0,a0,a1,a1}) so FFMA2's
// vector operand needs no packing. Grid = 128 blocks = 1/SM, one wave.

__global__ __launch_bounds__(256, 1)
void vgemm_bias_kernel(const float* __restrict__ A,    // [N, C] feat
                       const float* __restrict__ B,    // [C, C] Wv
                       const float* __restrict__ bias, // [C]
                       float* __restrict__ O)          // [N, C]
{
    __shared__ float sATd[2][KC][SATD_STRIDE];  // A, k-major, dup'd: 33.8 KB
    __shared__ float sB  [2][KC][TN];           // B, k-major:         8 KB

    const int tid  = threadIdx.x;   // 0..255
    const int lane = tid & 31;
    const int warp = tid >> 5;      // 0..7
    const int tn   = tid & 7;       // col group (x4)
    const int tm   = tid >> 3;      // row group (x2), 0..31

    const int row0 = blockIdx.y * TM;
    const int col0 = blockIdx.x * TN;

    // ---- register-staged global loads (LDG only; STS deferred) ----
    float  av[4][2];   // A values: 4 units x 2 rows
    float4 bv4;        // B values: one float4
    auto ldg_tiles = [&](int kk) {
        #pragma unroll
        for (int i = 0; i < 4; i++) {
            const int p = warp * 4 + i;            // row-pair 0..31
            const float* gp = &A[(row0 + 2 * p) * Cdim + kk + lane];
            av[i][0] = gp[0];
            av[i][1] = gp[Cdim];
        }
        const int r  = tid >> 3;        // 0..31
        const int c4 = (tid & 7) * 4;
        bv4 = *reinterpret_cast<const float4*>(&B[(kk + r) * Cdim + col0 + c4]);
    };
    auto sts_tiles = [&](int buf) {
        #pragma unroll
        for (int i = 0; i < 4; i++) {
            const int p = warp * 4 + i;
            float4 w = make_float4(av[i][0], av[i][0], av[i][1], av[i][1]);
            *reinterpret_cast<float4*>(&sATd[buf][lane][p * 4]) = w;
        }
        const int r  = tid >> 3;
        const int c4 = (tid & 7) * 4;
        *reinterpret_cast<float4*>(&sB[buf][r][c4]) = bv4;
    };

    unsigned long long acc00 = 0, acc01 = 0, acc10 = 0, acc11 = 0;

    ldg_tiles(0);
    sts_tiles(0);
    __syncthreads();

    for (int chunk = 0; chunk < CHUNKS; chunk++) {
        const int buf = chunk & 1;

        // issue next chunk's LDGs now; latency hidden under compute
        if (chunk + 1 < CHUNKS)
            ldg_tiles((chunk + 1) * KC);

        uint32_t aAddr = (uint32_t)__cvta_generic_to_shared(
            &sATd[buf][0][tm * 4]);
        uint32_t bAddr = (uint32_t)__cvta_generic_to_shared(
            &sB[buf][0][tn * 4]);

        #pragma unroll
        for (int g = 0; g < KC / KU; g++) {
            // ---- batch: 8 back-to-back LDS.128 for 4 k-iters ----
            unsigned long long a0[KU], a1[KU], b0[KU], b1[KU];
            #pragma unroll
            for (int u = 0; u < KU; u++) {
                lds_2x64(a0[u], a1[u], aAddr + u * (SATD_STRIDE * 4));
                lds_2x64(b0[u], b1[u], bAddr + u * (TN * 4));
            }
            aAddr += KU * (SATD_STRIDE * 4);
            bAddr += KU * (TN * 4);
            // ---- 16 FFMA2 on resident registers ----
            #pragma unroll
            for (int u = 0; u < KU; u++) {
                FMA2(acc00, a0[u], b0[u]);
                FMA2(acc01, a0[u], b1[u]);
                FMA2(acc10, a1[u], b0[u]);
                FMA2(acc11, a1[u], b1[u]);
            }
        }

        // store next chunk's tiles after compute, then barrier
        if (chunk + 1 < CHUNKS)
            sts_tiles(buf ^ 1);
        __syncthreads();
    }

    // ---- epilogue: unpack, bias add, float4 stores ----
    const int col = col0 + tn * 4;
    const float4 bb = *reinterpret_cast<const float4*>(&bias[col]);
    {
        const float2 lo = u64_as_f2(acc00);
        const float2 hi = u64_as_f2(acc01);
        float4 o = make_float4(lo.x + bb.x, lo.y + bb.y, hi.x + bb.z, hi.y + bb.w);
        *reinterpret_cast<float4*>(&O[(row0 + tm * 2 + 0) * Cdim + col]) = o;
    }
    {
        const float2 lo = u64_as_f2(acc10);
        const float2 hi = u64_as_f2(acc11);
        float4 o = make_float4(lo.x + bb.x, lo.y + bb.y, hi.x + bb.z, hi.y + bb.w);
        *reinterpret_cast<float4*>(&O[(row0 + tm * 2 + 1) * Cdim + col]) = o;
    }
}

} // namespace

extern "C" void kernel_launch(void* const* d_in, const int* in_sizes, int n_in,
                              void* d_out, int out_size)
{
    const float* feat = (const float*)d_in[0];
    const float* Wv   = (const float*)d_in[9];
    const float* bv   = (const float*)d_in[10];
    float* out        = (float*)d_out;

    dim3 grid(Cdim / TN, Ndim / TM);   // (8, 16) = 128 blocks
    dim3 block(256);
    vgemm_bias_kernel<<<grid, block>>>(feat, Wv, bv, out);
}

// round 11
// speedup vs baseline: 1.5055x; 1.4686x over previous
#include <cuda_runtime.h>
#include <cuda_bf16.h>
#include <cstdint>

// out = feat @ Wv + bv
//
// The reference's softmax over axis=-2 (j) followed by einsum('ijk,ik->ik')
// (a sum over j) makes the attention-weight branch sum to exactly 1 per
// (i,k), so out[i,k] == v[i,k] == (feat @ Wv + bv)[i,k].
//
// feat: [N=1024, C=256] f32   (d_in[0])
// Wv:   [C, C]          f32   (d_in[9])
// bv:   [C]             f32   (d_in[10])
// out:  [N, C]          f32
//
// R11: tensor cores via arch-generic PTX (tcgen05 is rejected by this
// harness's compute_103 lowering). Split precision:
//   x ~= hi + lo (bf16);  A*B ~= Ah*Bh + Ah*Bl + Al*Bh   (fp32 accum)
// mma.sync.m16n8k16.bf16 + ldmatrix, K=256 staged once in smem.

namespace {

constexpr int Cdim = 256;

// smem strides chosen for conflict-free ldmatrix:
//  A rows 264 bf16 = 528 B (132 words ≡ 4-bank shift/row -> 8 rows cover all banks)
//  B rows  40 bf16 =  80 B (20 words/row -> 8 k-rows hit 8 distinct bank groups)
constexpr uint32_t A_STRIDE_B = 528;
constexpr uint32_t B_STRIDE_B = 80;
constexpr uint32_t SM_AHI  = 0;
constexpr uint32_t SM_ALO  = SM_AHI + 64 * A_STRIDE_B;    // 33792
constexpr uint32_t SM_BHI  = SM_ALO + 64 * A_STRIDE_B;    // 67584
constexpr uint32_t SM_BLO  = SM_BHI + 256 * B_STRIDE_B;   // 88064
constexpr uint32_t SM_BIAS = SM_BLO + 256 * B_STRIDE_B;   // 108544
constexpr uint32_t SMEM_BYTES = SM_BIAS + 128;            // 108672 (< 227 KB dyn)

#define LDSM_X4(r0, r1, r2, r3, addr)                                        \
    asm volatile("ldmatrix.sync.aligned.m8n8.x4.shared.b16 {%0,%1,%2,%3}, [%4];" \
                 : "=r"(r0), "=r"(r1), "=r"(r2), "=r"(r3) : "r"(addr))

#define LDSM_X2T(r0, r1, addr)                                               \
    asm volatile("ldmatrix.sync.aligned.m8n8.x2.trans.shared.b16 {%0,%1}, [%2];" \
                 : "=r"(r0), "=r"(r1) : "r"(addr))

#define MMA_BF16(c, a0, a1, a2, a3, b0, b1)                                  \
    asm volatile("mma.sync.aligned.m16n8k16.row.col.f32.bf16.bf16.f32 "      \
                 "{%0,%1,%2,%3}, {%4,%5,%6,%7}, {%8,%9}, {%0,%1,%2,%3};"     \
                 : "+f"((c)[0]), "+f"((c)[1]), "+f"((c)[2]), "+f"((c)[3])    \
                 : "r"(a0), "r"(a1), "r"(a2), "r"(a3), "r"(b0), "r"(b1))

__device__ __forceinline__ uint32_t smem_u32(const void* p) {
    uint32_t a;
    asm("{ .reg .u64 t; cvta.to.shared.u64 t, %1; cvt.u32.u64 %0, t; }"
        : "=r"(a) : "l"(p));
    return a;
}

__device__ __forceinline__ uint32_t pack_bf2(float a, float b) {
    __nv_bfloat162 p = __floats2bfloat162_rn(a, b);
    return *reinterpret_cast<uint32_t*>(&p);
}

// split a float4 into hi (bf16) and lo (residual bf16), packed 2x per u32
__device__ __forceinline__ void split4(float4 f, uint2& hi, uint2& lo) {
    const float hx = __bfloat162float(__float2bfloat16(f.x));
    const float hy = __bfloat162float(__float2bfloat16(f.y));
    const float hz = __bfloat162float(__float2bfloat16(f.z));
    const float hw = __bfloat162float(__float2bfloat16(f.w));
    hi.x = pack_bf2(hx, hy);
    hi.y = pack_bf2(hz, hw);
    lo.x = pack_bf2(f.x - hx, f.y - hy);
    lo.y = pack_bf2(f.z - hz, f.w - hw);
}

// CTA: 64(M) x 32(N) tile, full K=256. 128 threads = 4 warps, each warp one
// m16 strip x 32 cols (4 n8 fragments). Grid (8, 16) = 128 CTAs, one wave.

__global__ __launch_bounds__(128, 1)
void vgemm_mma_kernel(const float* __restrict__ feat,  // [1024, 256]
                      const float* __restrict__ Wv,    // [256, 256]
                      const float* __restrict__ bias,  // [256]
                      float* __restrict__ O)           // [1024, 256]
{
    extern __shared__ char smem[];
    const uint32_t sb = smem_u32(smem);

    const int tid  = (int)threadIdx.x;   // 0..127
    const int warp = tid >> 5;
    const int lane = tid & 31;
    const int row0 = (int)blockIdx.y * 64;
    const int col0 = (int)blockIdx.x * 32;

    // ---- stage bias ----
    if (tid < 8) {
        reinterpret_cast<float4*>(smem + SM_BIAS)[tid] =
            reinterpret_cast<const float4*>(bias + col0)[tid];
    }

    // ---- load + split A: 64 x 256 f32 = 4096 float4; 32 per thread ----
    #pragma unroll
    for (int it = 0; it < 32; it++) {
        const int idx = it * 128 + tid;
        const int m   = idx >> 6;          // 64 float4 per row
        const int c4  = idx & 63;
        const float4 f = *reinterpret_cast<const float4*>(
            &feat[(row0 + m) * Cdim + c4 * 4]);
        uint2 hi, lo;
        split4(f, hi, lo);
        const uint32_t off = (uint32_t)m * A_STRIDE_B + (uint32_t)c4 * 8;
        *reinterpret_cast<uint2*>(smem + SM_AHI + off) = hi;
        *reinterpret_cast<uint2*>(smem + SM_ALO + off) = lo;
    }

    // ---- load + split B: Wv rows [k][col0..col0+32), 2048 float4; 16/thread ----
    #pragma unroll
    for (int it = 0; it < 16; it++) {
        const int idx = it * 128 + tid;
        const int k   = idx >> 3;          // 8 float4 per row
        const int c4  = idx & 7;
        const float4 f = *reinterpret_cast<const float4*>(
            &Wv[k * Cdim + col0 + c4 * 4]);
        uint2 hi, lo;
        split4(f, hi, lo);
        const uint32_t off = (uint32_t)k * B_STRIDE_B + (uint32_t)c4 * 8;
        *reinterpret_cast<uint2*>(smem + SM_BHI + off) = hi;
        *reinterpret_cast<uint2*>(smem + SM_BLO + off) = lo;
    }

    __syncthreads();

    // ---- tensor-core mainloop ----
    const int m0 = warp * 16;
    float acc[4][4];
    #pragma unroll
    for (int t = 0; t < 4; t++)
        #pragma unroll
        for (int i = 0; i < 4; i++) acc[t][i] = 0.f;

    // A ldmatrix.x4 addresses: lanes 0-15 -> 16 rows at k-half 0,
    // lanes 16-31 -> same rows at k-half 1 (+16 B).
    const uint32_t aHiBase = sb + SM_AHI +
        (uint32_t)(m0 + (lane & 15)) * A_STRIDE_B + (uint32_t)(lane >> 4) * 16;
    const uint32_t aLoBase = aHiBase + (SM_ALO - SM_AHI);
    // B ldmatrix.x2.trans addresses: lanes 0-15 -> 16 consecutive k-rows.
    const uint32_t bHiBase = sb + SM_BHI + (uint32_t)(lane & 15) * B_STRIDE_B;

    #pragma unroll
    for (int ks = 0; ks < 16; ks++) {
        uint32_t ah0, ah1, ah2, ah3, al0, al1, al2, al3;
        LDSM_X4(ah0, ah1, ah2, ah3, aHiBase + (uint32_t)ks * 32);
        LDSM_X4(al0, al1, al2, al3, aLoBase + (uint32_t)ks * 32);

        const uint32_t bk = bHiBase + (uint32_t)ks * (16 * B_STRIDE_B);
        #pragma unroll
        for (int t = 0; t < 4; t++) {
            uint32_t bh0, bh1, bl0, bl1;
            const uint32_t ba = bk + (uint32_t)t * 16;   // n0 = t*8 -> 16 B
            LDSM_X2T(bh0, bh1, ba);
            LDSM_X2T(bl0, bl1, ba + (SM_BLO - SM_BHI));
            MMA_BF16(acc[t], ah0, ah1, ah2, ah3, bh0, bh1);
            MMA_BF16(acc[t], ah0, ah1, ah2, ah3, bl0, bl1);
            MMA_BF16(acc[t], al0, al1, al2, al3, bh0, bh1);
        }
    }

    // ---- epilogue: bias add + stores (canonical m16n8 D mapping) ----
    const float* bs = reinterpret_cast<const float*>(smem + SM_BIAS);
    const int g  = lane >> 2;
    const int tc = (lane & 3) * 2;
    const int r1 = row0 + m0 + g;
    const int r2 = r1 + 8;
    #pragma unroll
    for (int t = 0; t < 4; t++) {
        const int n = t * 8 + tc;
        float2 o1, o2;
        o1.x = acc[t][0] + bs[n];
        o1.y = acc[t][1] + bs[n + 1];
        o2.x = acc[t][2] + bs[n];
        o2.y = acc[t][3] + bs[n + 1];
        *reinterpret_cast<float2*>(&O[r1 * Cdim + col0 + n]) = o1;
        *reinterpret_cast<float2*>(&O[r2 * Cdim + col0 + n]) = o2;
    }
}

} // namespace

extern "C" void kernel_launch(void* const* d_in, const int* in_sizes, int n_in,
                              void* d_out, int out_size)
{
    const float* feat = (const float*)d_in[0];
    const float* Wv   = (const float*)d_in[9];
    const float* bv   = (const float*)d_in[10];
    float* out        = (float*)d_out;

    cudaFuncSetAttribute(vgemm_mma_kernel,
                         cudaFuncAttributeMaxDynamicSharedMemorySize,
                         (int)SMEM_BYTES);
    dim3 grid(8, 16);   // 8 N-tiles x 16 M-tiles = 128 CTAs
    vgemm_mma_kernel<<<grid, 128, SMEM_BYTES>>>(feat, Wv, bv, out);
}